// round 13
// baseline (speedup 1.0000x reference)
#include <cuda_runtime.h>
#include <math.h>
#include <stdint.h>

#define BB 4
#define TT 2048
#define CC 1024
#define HH 16
#define DD 64
#define MROWS (BB*TT)     // 8192
#define NQKV  (3*CC)      // 3072

// Scratch (device globals — allocation-free per harness rules)
__device__ float g_q[BB*HH*TT*DD];   // tf32-rounded, pre-scaled by 0.125*log2(e)
__device__ float g_k[BB*HH*TT*DD];   // tf32-rounded
__device__ float g_v[BB*HH*TT*DD];   // tf32-rounded
__device__ float g_o[MROWS*CC];      // tf32-rounded attention output
__device__ float g_xr[MROWS*CC];     // tf32-rounded x
__device__ float g_wq[CC*NQKV];      // tf32-rounded w_qkv
__device__ float g_wp[CC*CC];        // tf32-rounded w_proj

__device__ __forceinline__ float to_tf32(float x) {
    float y;
    asm("cvt.rna.tf32.f32 %0, %1;" : "=f"(y) : "f"(x));
    return y;
}
__device__ __forceinline__ float ex2(float x) {
    float y;
    asm("ex2.approx.ftz.f32 %0, %1;" : "=f"(y) : "f"(x));
    return y;
}
__device__ __forceinline__ uint32_t sptr(const void* p) {
    return (uint32_t)__cvta_generic_to_shared(p);
}
__device__ __forceinline__ void cp16(uint32_t s, const void* g) {
    asm volatile("cp.async.cg.shared.global [%0], [%1], 16;\n" :: "r"(s), "l"(g));
}
__device__ __forceinline__ void cp_commit() {
    asm volatile("cp.async.commit_group;\n");
}
template<int N> __device__ __forceinline__ void cp_wait() {
    asm volatile("cp.async.wait_group %0;\n" :: "n"(N));
}

__device__ __forceinline__ void mma_tf32(float d[4], const float a[4], const float b[2]) {
    asm volatile(
        "mma.sync.aligned.m16n8k8.row.col.f32.tf32.tf32.f32 "
        "{%0,%1,%2,%3}, {%4,%5,%6,%7}, {%8,%9}, {%0,%1,%2,%3};\n"
        : "+f"(d[0]), "+f"(d[1]), "+f"(d[2]), "+f"(d[3])
        : "r"(__float_as_uint(a[0])), "r"(__float_as_uint(a[1])),
          "r"(__float_as_uint(a[2])), "r"(__float_as_uint(a[3])),
          "r"(__float_as_uint(b[0])), "r"(__float_as_uint(b[1])));
}

// ---------------------------------------------------------------------------
// One-time tf32 rounding pass (vectorized elementwise)
// ---------------------------------------------------------------------------
__global__ __launch_bounds__(256) void round_pass(
    const float* __restrict__ src, float* __restrict__ dst)
{
    const size_t i = ((size_t)blockIdx.x * 256 + threadIdx.x) * 4;
    float4 v = *(const float4*)(src + i);
    v.x = to_tf32(v.x); v.y = to_tf32(v.y);
    v.z = to_tf32(v.z); v.w = to_tf32(v.w);
    *(float4*)(dst + i) = v;
}

// ---------------------------------------------------------------------------
// tf32 mma.sync GEMM with FRAGMENT-ORDERED smem:
// each thread's mma operands are contiguous -> A frag = 1 LDS.128,
// B frag = 1 LDS.64 (was 4 + 2 LDS.32). Register-staged LDG pipeline kept.
//   A layout: idx = ((ks*8 + M16)*32 + lane)*4 + (half_k*2 + half_m)
//   B layout: idx = ((ks*16 + N8)*32 + lane)*2 + half_k
// Buffers: A 2048 floats, B 2048 floats -> 32KB total (2 bufs).
// Block 128x128, BK=16, 8 warps (2x4), warp tile 64x32.
// mode 0: QKV epilogue (scatter tf32-rounded to g_q/g_k/g_v)
// mode 1: proj epilogue (write fp32 to out)
// ---------------------------------------------------------------------------
#define AFSZ 2048
#define BFSZ 2048

__global__ __launch_bounds__(256, 2) void gemm_tf32(
    const float* __restrict__ A, const float* __restrict__ Bw,
    const float* __restrict__ bias, float* __restrict__ out,
    int N, int mode)
{
    __shared__ __align__(16) float As[2][AFSZ];
    __shared__ __align__(16) float Bs[2][BFSZ];

    const int tid  = threadIdx.x;
    const int lane = tid & 31;
    const int wid  = tid >> 5;
    const int g    = lane >> 2;
    const int t4   = lane & 3;
    const int warp_m = (wid >> 2) * 64;
    const int warp_n = (wid & 3) * 32;
    const int m0 = blockIdx.y * 128;
    const int n0 = blockIdx.x * 128;

    const int ar = tid >> 2;          // A row 0..63 (+64 second half)
    const int ak = (tid & 3) * 4;     // A k offset (0,4,8,12)
    const int br = tid >> 4;          // B k-row 0..15
    const int bc = (tid & 15) * 4;    // B n offset (0..60 by 4), second +64

    // precomputed store bases
    const int a_ks = ak >> 3;
    const int a_hk = (ak >> 2) & 1;
    const int b_ks = br >> 3;
    const int b_t4 = br & 3;
    const int b_hk = (br >> 2) & 1;

    float acc[4][4][4];
    #pragma unroll
    for (int i = 0; i < 4; i++)
        #pragma unroll
        for (int j = 0; j < 4; j++)
            #pragma unroll
            for (int r = 0; r < 4; r++) acc[i][j][r] = 0.f;

    float4 a_s[2], b_s[2];

    auto ldg_tile = [&](int k0) {
        a_s[0] = *(const float4*)(A + (size_t)(m0 + ar) * CC + k0 + ak);
        a_s[1] = *(const float4*)(A + (size_t)(m0 + ar + 64) * CC + k0 + ak);
        b_s[0] = *(const float4*)(Bw + (size_t)(k0 + br) * N + n0 + bc);
        b_s[1] = *(const float4*)(Bw + (size_t)(k0 + br) * N + n0 + bc + 64);
    };
    auto sts_tile = [&](int buf) {
        #pragma unroll
        for (int h = 0; h < 2; h++) {
            const int m   = ar + h * 64;
            const int M16 = m >> 4;
            const int mg  = m & 7;
            const int hm  = (m >> 3) & 1;
            float* dst = &As[buf][(((a_ks * 8 + M16) * 32) + mg * 4) * 4 + a_hk * 2 + hm];
            const float4 a4 = a_s[h];
            dst[0]  = a4.x;   // i=0 -> +4*0
            dst[4]  = a4.y;
            dst[8]  = a4.z;
            dst[12] = a4.w;
        }
        #pragma unroll
        for (int h = 0; h < 2; h++) {
            const int n  = bc + h * 64;
            const int N8 = n >> 3;
            const int gb = n & 7;     // 0 or 4
            float* dst = &Bs[buf][(((b_ks * 16 + N8) * 32) + gb * 4 + b_t4) * 2 + b_hk];
            const float4 b4 = b_s[h];
            dst[0]  = b4.x;   // i -> +8*i (g step of 1 -> lane step 4 -> *2)
            dst[8]  = b4.y;
            dst[16] = b4.z;
            dst[24] = b4.w;
        }
    };

    ldg_tile(0);
    sts_tile(0);
    __syncthreads();

    const int wM16 = warp_m >> 4;     // 0 or 4
    const int wN8  = warp_n >> 3;     // 0,4,8,12

    for (int k0 = 0; k0 < CC; k0 += 16) {
        const int buf = (k0 >> 4) & 1;
        const bool pf = (k0 + 16) < CC;
        if (pf) ldg_tile(k0 + 16);       // LDG latency hidden behind mmas

        #pragma unroll
        for (int ks = 0; ks < 2; ks++) {
            float af[4][4], bf[4][2];
            #pragma unroll
            for (int mt = 0; mt < 4; mt++) {
                const float4 a4 = *(const float4*)
                    &As[buf][((ks * 8 + wM16 + mt) * 32 + lane) * 4];
                af[mt][0] = a4.x; af[mt][1] = a4.y;
                af[mt][2] = a4.z; af[mt][3] = a4.w;
            }
            #pragma unroll
            for (int nt = 0; nt < 4; nt++) {
                const float2 b2 = *(const float2*)
                    &Bs[buf][((ks * 16 + wN8 + nt) * 32 + lane) * 2];
                bf[nt][0] = b2.x; bf[nt][1] = b2.y;
            }
            #pragma unroll
            for (int mt = 0; mt < 4; mt++)
                #pragma unroll
                for (int nt = 0; nt < 4; nt++)
                    mma_tf32(acc[mt][nt], af[mt], bf[nt]);
        }

        if (pf) sts_tile(buf ^ 1);
        __syncthreads();
    }

    #pragma unroll
    for (int mt = 0; mt < 4; mt++) {
        #pragma unroll
        for (int half = 0; half < 2; half++) {
            const int m = m0 + warp_m + mt * 16 + g + half * 8;
            #pragma unroll
            for (int nt = 0; nt < 4; nt++) {
                const int n = n0 + warp_n + nt * 8 + t4 * 2;
                float v0 = acc[mt][nt][half * 2 + 0] + bias[n];
                float v1 = acc[mt][nt][half * 2 + 1] + bias[n + 1];
                if (mode == 1) {
                    *(float2*)(out + (size_t)m * CC + n) = make_float2(v0, v1);
                } else {
                    const int s  = n >> 10;            // 0:q 1:k 2:v
                    const int h  = (n & 1023) >> 6;
                    const int d  = n & 63;
                    const int bidx = m >> 11;
                    const int t = m & (TT - 1);
                    const size_t idx = (((size_t)(bidx * HH + h)) * TT + t) * DD + d;
                    const float QS = 0.125f * 1.44269504f;  // 1/sqrt(D) * log2(e)
                    if (s == 0)
                        *(float2*)(g_q + idx) = make_float2(to_tf32(v0 * QS), to_tf32(v1 * QS));
                    else if (s == 1)
                        *(float2*)(g_k + idx) = make_float2(to_tf32(v0), to_tf32(v1));
                    else
                        *(float2*)(g_v + idx) = make_float2(to_tf32(v0), to_tf32(v1));
                }
            }
        }
    }
}

// ---------------------------------------------------------------------------
// Tensor-core causal flash attention (UNCHANGED from passing R12 config).
// 128-query CTA, 8 warps, K+V double-buffered, 1 sync + 1 wait per tile,
// fixed-max softmax, deferred row-sum, diagonal-masked warps skip compute.
// ---------------------------------------------------------------------------
#define KPK 68
#define KPV 72
#define PP  36
#define NW  8
#define ATTN_SMEM ((2*64*KPK + 2*64*KPV + NW*16*PP) * 4)   // 90112 B

__global__ __launch_bounds__(256, 2) void attn_tc()
{
    extern __shared__ __align__(16) float dsm[];
    float* Ks = dsm;                               // [2][64*KPK]
    float* Vs = dsm + 2 * 64 * KPK;                // [2][64*KPV]
    float* Ps = dsm + 2 * 64 * KPK + 2 * 64 * KPV; // [NW][16*PP]

    const int qt  = (int)gridDim.x - 1 - (int)blockIdx.x;  // heavy tiles first
    const int h   = blockIdx.y;
    const int b   = blockIdx.z;
    const int tid  = threadIdx.x;
    const int lane = tid & 31;
    const int w    = tid >> 5;           // 0..7
    const int g    = lane >> 2;
    const int t4   = lane & 3;

    const size_t head_off = ((size_t)(b * HH + h)) * TT * DD;
    const float* __restrict__ qb = g_q + head_off;
    const float* __restrict__ kb = g_k + head_off;
    const float* __restrict__ vb = g_v + head_off;

    const int srow = tid >> 2;           // 0..63
    const int scol = (tid & 3) * 16;

    auto issue_kv = [&](int jt, int buf) {
        const float* ksrc = kb + (size_t)(jt * 64 + srow) * DD + scol;
        uint32_t kdst = sptr(&Ks[buf * 64 * KPK + srow * KPK + scol]);
        #pragma unroll
        for (int c = 0; c < 16; c += 4) cp16(kdst + c * 4, ksrc + c);
        const float* vsrc = vb + (size_t)(jt * 64 + srow) * DD + scol;
        uint32_t vdst = sptr(&Vs[buf * 64 * KPV + srow * KPV + scol]);
        #pragma unroll
        for (int c = 0; c < 16; c += 4) cp16(vdst + c * 4, vsrc + c);
        cp_commit();
    };

    float qf[8][4];
    {
        const int r0 = qt * 128 + w * 16 + g;
        #pragma unroll
        for (int kc = 0; kc < 8; kc++) {
            qf[kc][0] = qb[(size_t)r0 * DD + kc * 8 + t4];
            qf[kc][1] = qb[(size_t)(r0 + 8) * DD + kc * 8 + t4];
            qf[kc][2] = qb[(size_t)r0 * DD + kc * 8 + t4 + 4];
            qf[kc][3] = qb[(size_t)(r0 + 8) * DD + kc * 8 + t4 + 4];
        }
    }

    float o[8][4];
    #pragma unroll
    for (int nt = 0; nt < 8; nt++)
        #pragma unroll
        for (int r = 0; r < 4; r++) o[nt][r] = 0.f;
    float l0 = 0.f, l1 = 0.f;

    float* pb = Ps + w * 16 * PP;

    issue_kv(0, 0);

    const int njt = 2 * qt + 2;

    for (int jt = 0; jt < njt; jt++) {
        const int buf = jt & 1;

        cp_wait<0>();
        __syncthreads();
        if (jt + 1 < njt) issue_kv(jt + 1, buf ^ 1);

        const bool active = !(jt == 2 * qt + 1 && w < 4);
        if (active) {
            float s[8][4];
            #pragma unroll
            for (int nt = 0; nt < 8; nt++)
                #pragma unroll
                for (int r = 0; r < 4; r++) s[nt][r] = 0.f;

            const float* kbuf = Ks + buf * 64 * KPK;
            #pragma unroll
            for (int kc = 0; kc < 8; kc++) {
                #pragma unroll
                for (int nt = 0; nt < 8; nt++) {
                    float bk[2];
                    bk[0] = kbuf[(nt * 8 + g) * KPK + kc * 8 + t4];
                    bk[1] = kbuf[(nt * 8 + g) * KPK + kc * 8 + t4 + 4];
                    mma_tf32(s[nt], qf[kc], bk);
                }
            }

            if (jt >= 2 * qt) {
                const int rlo = w * 16 + g - (jt - 2 * qt) * 64;
                const int rhi = rlo + 8;
                #pragma unroll
                for (int nt = 0; nt < 8; nt++) {
                    const int col = nt * 8 + 2 * t4;
                    if (col     > rlo) s[nt][0] = -1e30f;
                    if (col + 1 > rlo) s[nt][1] = -1e30f;
                    if (col     > rhi) s[nt][2] = -1e30f;
                    if (col + 1 > rhi) s[nt][3] = -1e30f;
                }
            }

            #pragma unroll
            for (int nt = 0; nt < 8; nt++) {
                s[nt][0] = ex2(s[nt][0]);
                s[nt][1] = ex2(s[nt][1]);
                s[nt][2] = ex2(s[nt][2]);
                s[nt][3] = ex2(s[nt][3]);
                l0 += s[nt][0] + s[nt][1];
                l1 += s[nt][2] + s[nt][3];
            }

            const float* vbuf = Vs + buf * 64 * KPV;
            #pragma unroll
            for (int half = 0; half < 2; half++) {
                #pragma unroll
                for (int q = 0; q < 4; q++) {
                    const int nt = half * 4 + q;
                    const int col = q * 8 + 2 * t4;
                    *(float2*)&pb[g * PP + col] =
                        make_float2(to_tf32(s[nt][0]), to_tf32(s[nt][1]));
                    *(float2*)&pb[(g + 8) * PP + col] =
                        make_float2(to_tf32(s[nt][2]), to_tf32(s[nt][3]));
                }
                __syncwarp();
                #pragma unroll
                for (int kc2 = 0; kc2 < 4; kc2++) {
                    const int kc = half * 4 + kc2;
                    float a[4];
                    a[0] = pb[g * PP + kc2 * 8 + t4];
                    a[1] = pb[(g + 8) * PP + kc2 * 8 + t4];
                    a[2] = pb[g * PP + kc2 * 8 + t4 + 4];
                    a[3] = pb[(g + 8) * PP + kc2 * 8 + t4 + 4];
                    #pragma unroll
                    for (int nt = 0; nt < 8; nt++) {
                        float bv[2];
                        bv[0] = vbuf[(kc * 8 + t4) * KPV + nt * 8 + g];
                        bv[1] = vbuf[(kc * 8 + t4 + 4) * KPV + nt * 8 + g];
                        mma_tf32(o[nt], a, bv);
                    }
                }
                __syncwarp();
            }
        }
    }

    l0 += __shfl_xor_sync(0xffffffffu, l0, 1);
    l0 += __shfl_xor_sync(0xffffffffu, l0, 2);
    l1 += __shfl_xor_sync(0xffffffffu, l1, 1);
    l1 += __shfl_xor_sync(0xffffffffu, l1, 2);
    const float i0 = 1.f / l0;
    const float i1 = 1.f / l1;
    const int qrow = qt * 128 + w * 16;
    float* ob = g_o + ((size_t)(b * TT) + qrow) * CC + h * DD;
    #pragma unroll
    for (int nt = 0; nt < 8; nt++) {
        const int d = nt * 8 + 2 * t4;
        *(float2*)(ob + (size_t)g * CC + d) =
            make_float2(to_tf32(o[nt][0] * i0), to_tf32(o[nt][1] * i0));
        *(float2*)(ob + (size_t)(g + 8) * CC + d) =
            make_float2(to_tf32(o[nt][2] * i1), to_tf32(o[nt][3] * i1));
    }
}

extern "C" void kernel_launch(void* const* d_in, const int* in_sizes, int n_in,
                              void* d_out, int out_size)
{
    const float* x      = (const float*)d_in[0];
    const float* w_qkv  = (const float*)d_in[1];
    const float* b_qkv  = (const float*)d_in[2];
    const float* w_proj = (const float*)d_in[3];
    const float* b_proj = (const float*)d_in[4];
    float* out = (float*)d_out;

    float *d_xr, *d_wq, *d_wp, *d_o;
    cudaGetSymbolAddress((void**)&d_xr, g_xr);
    cudaGetSymbolAddress((void**)&d_wq, g_wq);
    cudaGetSymbolAddress((void**)&d_wp, g_wp);
    cudaGetSymbolAddress((void**)&d_o,  g_o);

    cudaFuncSetAttribute(attn_tc, cudaFuncAttributeMaxDynamicSharedMemorySize,
                         ATTN_SMEM);

    // one-time tf32 pre-rounding
    round_pass<<<(MROWS * CC) / 1024, 256>>>(x, d_xr);
    round_pass<<<(CC * NQKV) / 1024, 256>>>(w_qkv, d_wq);
    round_pass<<<(CC * CC) / 1024, 256>>>(w_proj, d_wp);

    dim3 g1(NQKV / 128, MROWS / 128);   // (24, 64)
    gemm_tf32<<<g1, 256>>>(d_xr, d_wq, b_qkv, nullptr, NQKV, 0);

    dim3 g2(TT / 128, HH, BB);          // (16, 16, 4)
    attn_tc<<<g2, 256, ATTN_SMEM>>>();

    dim3 g3(CC / 128, MROWS / 128);     // (8, 64)
    gemm_tf32<<<g3, 256>>>(d_o, d_wp, b_proj, out, CC, 1);
}

// round 14
// speedup vs baseline: 1.5990x; 1.5990x over previous
#include <cuda_runtime.h>
#include <math.h>
#include <stdint.h>

#define BB 4
#define TT 2048
#define CC 1024
#define HH 16
#define DD 64
#define MROWS (BB*TT)     // 8192
#define NQKV  (3*CC)      // 3072

// Scratch (device globals — allocation-free per harness rules)
__device__ float g_q[BB*HH*TT*DD];   // tf32-rounded, pre-scaled by 0.125*log2(e)
__device__ float g_k[BB*HH*TT*DD];   // tf32-rounded
__device__ float g_v[BB*HH*TT*DD];   // tf32-rounded
__device__ float g_o[MROWS*CC];      // tf32-rounded attention output
__device__ float g_xr[MROWS*CC];     // tf32-rounded x
__device__ float g_wq[CC*NQKV];      // tf32-rounded w_qkv
__device__ float g_wp[CC*CC];       // tf32-rounded w_proj

__device__ __forceinline__ float to_tf32(float x) {
    float y;
    asm("cvt.rna.tf32.f32 %0, %1;" : "=f"(y) : "f"(x));
    return y;
}
__device__ __forceinline__ float ex2(float x) {
    float y;
    asm("ex2.approx.ftz.f32 %0, %1;" : "=f"(y) : "f"(x));
    return y;
}
__device__ __forceinline__ uint32_t sptr(const void* p) {
    return (uint32_t)__cvta_generic_to_shared(p);
}
__device__ __forceinline__ void cp16(uint32_t s, const void* g) {
    asm volatile("cp.async.cg.shared.global [%0], [%1], 16;\n" :: "r"(s), "l"(g));
}
__device__ __forceinline__ void cp_commit() {
    asm volatile("cp.async.commit_group;\n");
}
template<int N> __device__ __forceinline__ void cp_wait() {
    asm volatile("cp.async.wait_group %0;\n" :: "n"(N));
}

__device__ __forceinline__ void mma_tf32(float d[4], const float a[4], const float b[2]) {
    asm volatile(
        "mma.sync.aligned.m16n8k8.row.col.f32.tf32.tf32.f32 "
        "{%0,%1,%2,%3}, {%4,%5,%6,%7}, {%8,%9}, {%0,%1,%2,%3};\n"
        : "+f"(d[0]), "+f"(d[1]), "+f"(d[2]), "+f"(d[3])
        : "r"(__float_as_uint(a[0])), "r"(__float_as_uint(a[1])),
          "r"(__float_as_uint(a[2])), "r"(__float_as_uint(a[3])),
          "r"(__float_as_uint(b[0])), "r"(__float_as_uint(b[1])));
}

// ---------------------------------------------------------------------------
// One-time tf32 rounding, all three tensors in ONE launch.
// Segments (in 1024-float blocks): x 8192, w_qkv 3072, w_proj 1024.
// ---------------------------------------------------------------------------
__global__ __launch_bounds__(256) void round_all(
    const float* __restrict__ x,  float* __restrict__ dx,
    const float* __restrict__ wq, float* __restrict__ dwq,
    const float* __restrict__ wp, float* __restrict__ dwp)
{
    const int bid = blockIdx.x;
    const float* src;
    float* dst;
    size_t base;
    if (bid < 8192)      { src = x;  dst = dx;  base = bid; }
    else if (bid < 11264){ src = wq; dst = dwq; base = bid - 8192; }
    else                 { src = wp; dst = dwp; base = bid - 11264; }
    const size_t i = (base * 256 + threadIdx.x) * 4;
    float4 v = *(const float4*)(src + i);
    v.x = to_tf32(v.x); v.y = to_tf32(v.y);
    v.z = to_tf32(v.z); v.w = to_tf32(v.w);
    *(float4*)(dst + i) = v;
}

#define SPITCH 136   // gemm smem pitch (floats)

// ---------------------------------------------------------------------------
// tf32 mma.sync GEMM — register-staged BK=16 double-buffered pipeline
// (measured plateau config, R12; unchanged).
// ---------------------------------------------------------------------------
__global__ __launch_bounds__(256, 2) void gemm_tf32(
    const float* __restrict__ A, const float* __restrict__ Bw,
    const float* __restrict__ bias, float* __restrict__ out,
    int N, int mode)
{
    __shared__ float As[2][16 * SPITCH];
    __shared__ float Bs[2][16 * SPITCH];

    const int tid  = threadIdx.x;
    const int lane = tid & 31;
    const int wid  = tid >> 5;
    const int g    = lane >> 2;
    const int t4   = lane & 3;
    const int warp_m = (wid >> 2) * 64;
    const int warp_n = (wid & 3) * 32;
    const int m0 = blockIdx.y * 128;
    const int n0 = blockIdx.x * 128;

    const int ar = tid >> 2;
    const int ak = (tid & 3) * 4;
    const int br = tid >> 4;
    const int bc = (tid & 15) * 4;

    float acc[4][4][4];
    #pragma unroll
    for (int i = 0; i < 4; i++)
        #pragma unroll
        for (int j = 0; j < 4; j++)
            #pragma unroll
            for (int r = 0; r < 4; r++) acc[i][j][r] = 0.f;

    float4 a_s[2], b_s[2];

    auto ldg_tile = [&](int k0) {
        a_s[0] = *(const float4*)(A + (size_t)(m0 + ar) * CC + k0 + ak);
        a_s[1] = *(const float4*)(A + (size_t)(m0 + ar + 64) * CC + k0 + ak);
        b_s[0] = *(const float4*)(Bw + (size_t)(k0 + br) * N + n0 + bc);
        b_s[1] = *(const float4*)(Bw + (size_t)(k0 + br) * N + n0 + bc + 64);
    };
    auto sts_tile = [&](int buf) {
        #pragma unroll
        for (int h = 0; h < 2; h++) {
            const int m = ar + h * 64;
            const float4 a4 = a_s[h];
            As[buf][(ak + 0) * SPITCH + m] = a4.x;
            As[buf][(ak + 1) * SPITCH + m] = a4.y;
            As[buf][(ak + 2) * SPITCH + m] = a4.z;
            As[buf][(ak + 3) * SPITCH + m] = a4.w;
        }
        #pragma unroll
        for (int h = 0; h < 2; h++)
            *(float4*)&Bs[buf][br * SPITCH + bc + h * 64] = b_s[h];
    };

    ldg_tile(0);
    sts_tile(0);
    __syncthreads();

    for (int k0 = 0; k0 < CC; k0 += 16) {
        const int buf = (k0 >> 4) & 1;
        const bool pf = (k0 + 16) < CC;
        if (pf) ldg_tile(k0 + 16);       // LDG latency hidden behind mmas

        #pragma unroll
        for (int ks = 0; ks < 2; ks++) {
            const int kb = ks * 8;
            float af[4][4], bf[4][2];
            #pragma unroll
            for (int mt = 0; mt < 4; mt++) {
                const int m = warp_m + mt * 16 + g;
                af[mt][0] = As[buf][(kb + t4) * SPITCH + m];
                af[mt][1] = As[buf][(kb + t4) * SPITCH + m + 8];
                af[mt][2] = As[buf][(kb + t4 + 4) * SPITCH + m];
                af[mt][3] = As[buf][(kb + t4 + 4) * SPITCH + m + 8];
            }
            #pragma unroll
            for (int nt = 0; nt < 4; nt++) {
                const int n = warp_n + nt * 8 + g;
                bf[nt][0] = Bs[buf][(kb + t4) * SPITCH + n];
                bf[nt][1] = Bs[buf][(kb + t4 + 4) * SPITCH + n];
            }
            #pragma unroll
            for (int mt = 0; mt < 4; mt++)
                #pragma unroll
                for (int nt = 0; nt < 4; nt++)
                    mma_tf32(acc[mt][nt], af[mt], bf[nt]);
        }

        if (pf) sts_tile(buf ^ 1);
        __syncthreads();
    }

    #pragma unroll
    for (int mt = 0; mt < 4; mt++) {
        #pragma unroll
        for (int half = 0; half < 2; half++) {
            const int m = m0 + warp_m + mt * 16 + g + half * 8;
            #pragma unroll
            for (int nt = 0; nt < 4; nt++) {
                const int n = n0 + warp_n + nt * 8 + t4 * 2;
                float v0 = acc[mt][nt][half * 2 + 0] + bias[n];
                float v1 = acc[mt][nt][half * 2 + 1] + bias[n + 1];
                if (mode == 1) {
                    *(float2*)(out + (size_t)m * CC + n) = make_float2(v0, v1);
                } else {
                    const int s  = n >> 10;            // 0:q 1:k 2:v
                    const int h  = (n & 1023) >> 6;
                    const int d  = n & 63;
                    const int bidx = m >> 11;
                    const int t = m & (TT - 1);
                    const size_t idx = (((size_t)(bidx * HH + h)) * TT + t) * DD + d;
                    const float QS = 0.125f * 1.44269504f;  // 1/sqrt(D) * log2(e)
                    if (s == 0)
                        *(float2*)(g_q + idx) = make_float2(to_tf32(v0 * QS), to_tf32(v1 * QS));
                    else if (s == 1)
                        *(float2*)(g_k + idx) = make_float2(to_tf32(v0), to_tf32(v1));
                    else
                        *(float2*)(g_v + idx) = make_float2(to_tf32(v0), to_tf32(v1));
                }
            }
        }
    }
}

// ---------------------------------------------------------------------------
// Tensor-core causal flash attention (R12 structure) + diagonal-tile key-block
// skipping: on tiles jt >= 2qt, warp w only computes key blocks nt < ntlim
// (ntlim warp-uniform). Skipped blocks' S entries are mask-forced to -1e30
// anyway, so skipping their mma/route/PV is numerically exact.
// 128-query CTA, 8 warps, K+V double-buffered, 1 sync + 1 wait per tile.
// ---------------------------------------------------------------------------
#define KPK 68
#define KPV 72
#define PP  36
#define NW  8
#define ATTN_SMEM ((2*64*KPK + 2*64*KPV + NW*16*PP) * 4)   // 90112 B

__global__ __launch_bounds__(256, 2) void attn_tc()
{
    extern __shared__ __align__(16) float dsm[];
    float* Ks = dsm;                               // [2][64*KPK]
    float* Vs = dsm + 2 * 64 * KPK;                // [2][64*KPV]
    float* Ps = dsm + 2 * 64 * KPK + 2 * 64 * KPV; // [NW][16*PP]

    const int qt  = (int)gridDim.x - 1 - (int)blockIdx.x;  // heavy tiles first
    const int h   = blockIdx.y;
    const int b   = blockIdx.z;
    const int tid  = threadIdx.x;
    const int lane = tid & 31;
    const int w    = tid >> 5;           // 0..7
    const int g    = lane >> 2;
    const int t4   = lane & 3;

    const size_t head_off = ((size_t)(b * HH + h)) * TT * DD;
    const float* __restrict__ qb = g_q + head_off;
    const float* __restrict__ kb = g_k + head_off;
    const float* __restrict__ vb = g_v + head_off;

    const int srow = tid >> 2;           // 0..63
    const int scol = (tid & 3) * 16;

    auto issue_kv = [&](int jt, int buf) {
        const float* ksrc = kb + (size_t)(jt * 64 + srow) * DD + scol;
        uint32_t kdst = sptr(&Ks[buf * 64 * KPK + srow * KPK + scol]);
        #pragma unroll
        for (int c = 0; c < 16; c += 4) cp16(kdst + c * 4, ksrc + c);
        const float* vsrc = vb + (size_t)(jt * 64 + srow) * DD + scol;
        uint32_t vdst = sptr(&Vs[buf * 64 * KPV + srow * KPV + scol]);
        #pragma unroll
        for (int c = 0; c < 16; c += 4) cp16(vdst + c * 4, vsrc + c);
        cp_commit();
    };

    float qf[8][4];
    {
        const int r0 = qt * 128 + w * 16 + g;
        #pragma unroll
        for (int kc = 0; kc < 8; kc++) {
            qf[kc][0] = qb[(size_t)r0 * DD + kc * 8 + t4];
            qf[kc][1] = qb[(size_t)(r0 + 8) * DD + kc * 8 + t4];
            qf[kc][2] = qb[(size_t)r0 * DD + kc * 8 + t4 + 4];
            qf[kc][3] = qb[(size_t)(r0 + 8) * DD + kc * 8 + t4 + 4];
        }
    }

    float o[8][4];
    #pragma unroll
    for (int nt = 0; nt < 8; nt++)
        #pragma unroll
        for (int r = 0; r < 4; r++) o[nt][r] = 0.f;
    float l0 = 0.f, l1 = 0.f;

    float* pb = Ps + w * 16 * PP;

    issue_kv(0, 0);

    const int njt = 2 * qt + 2;

    for (int jt = 0; jt < njt; jt++) {
        const int buf = jt & 1;

        cp_wait<0>();
        __syncthreads();
        if (jt + 1 < njt) issue_kv(jt + 1, buf ^ 1);

        const bool active = !(jt == 2 * qt + 1 && w < 4);
        if (active) {
            // live key-block bound for diagonal tiles (warp-uniform)
            int ntlim = 8;
            if (jt >= 2 * qt) {
                const int rl = w * 16 + 15 - (jt - 2 * qt) * 64;  // warp max row
                ntlim = (rl >> 3) + 1;
                if (ntlim > 8) ntlim = 8;
            }

            float s[8][4];
            #pragma unroll
            for (int nt = 0; nt < 8; nt++)
                #pragma unroll
                for (int r = 0; r < 4; r++) s[nt][r] = 0.f;

            const float* kbuf = Ks + buf * 64 * KPK;
            #pragma unroll
            for (int nt = 0; nt < 8; nt++) {
                if (nt < ntlim) {
                    #pragma unroll
                    for (int kc = 0; kc < 8; kc++) {
                        float bk[2];
                        bk[0] = kbuf[(nt * 8 + g) * KPK + kc * 8 + t4];
                        bk[1] = kbuf[(nt * 8 + g) * KPK + kc * 8 + t4 + 4];
                        mma_tf32(s[nt], qf[kc], bk);
                    }
                }
            }

            if (jt >= 2 * qt) {
                const int rlo = w * 16 + g - (jt - 2 * qt) * 64;
                const int rhi = rlo + 8;
                #pragma unroll
                for (int nt = 0; nt < 8; nt++) {
                    const int col = nt * 8 + 2 * t4;
                    if (col     > rlo) s[nt][0] = -1e30f;
                    if (col + 1 > rlo) s[nt][1] = -1e30f;
                    if (col     > rhi) s[nt][2] = -1e30f;
                    if (col + 1 > rhi) s[nt][3] = -1e30f;
                }
            }

            #pragma unroll
            for (int nt = 0; nt < 8; nt++) {
                s[nt][0] = ex2(s[nt][0]);
                s[nt][1] = ex2(s[nt][1]);
                s[nt][2] = ex2(s[nt][2]);
                s[nt][3] = ex2(s[nt][3]);
                l0 += s[nt][0] + s[nt][1];
                l1 += s[nt][2] + s[nt][3];
            }

            const float* vbuf = Vs + buf * 64 * KPV;
            #pragma unroll
            for (int half = 0; half < 2; half++) {
                if (half * 4 < ntlim) {
                    #pragma unroll
                    for (int q = 0; q < 4; q++) {
                        const int nt = half * 4 + q;
                        if (nt < ntlim) {
                            const int col = q * 8 + 2 * t4;
                            *(float2*)&pb[g * PP + col] =
                                make_float2(to_tf32(s[nt][0]), to_tf32(s[nt][1]));
                            *(float2*)&pb[(g + 8) * PP + col] =
                                make_float2(to_tf32(s[nt][2]), to_tf32(s[nt][3]));
                        }
                    }
                    __syncwarp();
                    #pragma unroll
                    for (int kc2 = 0; kc2 < 4; kc2++) {
                        const int kc = half * 4 + kc2;
                        if (kc < ntlim) {
                            float a[4];
                            a[0] = pb[g * PP + kc2 * 8 + t4];
                            a[1] = pb[(g + 8) * PP + kc2 * 8 + t4];
                            a[2] = pb[g * PP + kc2 * 8 + t4 + 4];
                            a[3] = pb[(g + 8) * PP + kc2 * 8 + t4 + 4];
                            #pragma unroll
                            for (int nt = 0; nt < 8; nt++) {
                                float bv[2];
                                bv[0] = vbuf[(kc * 8 + t4) * KPV + nt * 8 + g];
                                bv[1] = vbuf[(kc * 8 + t4 + 4) * KPV + nt * 8 + g];
                                mma_tf32(o[nt], a, bv);
                            }
                        }
                    }
                    __syncwarp();
                }
            }
        }
    }

    l0 += __shfl_xor_sync(0xffffffffu, l0, 1);
    l0 += __shfl_xor_sync(0xffffffffu, l0, 2);
    l1 += __shfl_xor_sync(0xffffffffu, l1, 1);
    l1 += __shfl_xor_sync(0xffffffffu, l1, 2);
    const float i0 = 1.f / l0;
    const float i1 = 1.f / l1;
    const int qrow = qt * 128 + w * 16;
    float* ob = g_o + ((size_t)(b * TT) + qrow) * CC + h * DD;
    #pragma unroll
    for (int nt = 0; nt < 8; nt++) {
        const int d = nt * 8 + 2 * t4;
        *(float2*)(ob + (size_t)g * CC + d) =
            make_float2(to_tf32(o[nt][0] * i0), to_tf32(o[nt][1] * i0));
        *(float2*)(ob + (size_t)(g + 8) * CC + d) =
            make_float2(to_tf32(o[nt][2] * i1), to_tf32(o[nt][3] * i1));
    }
}

extern "C" void kernel_launch(void* const* d_in, const int* in_sizes, int n_in,
                              void* d_out, int out_size)
{
    const float* x      = (const float*)d_in[0];
    const float* w_qkv  = (const float*)d_in[1];
    const float* b_qkv  = (const float*)d_in[2];
    const float* w_proj = (const float*)d_in[3];
    const float* b_proj = (const float*)d_in[4];
    float* out = (float*)d_out;

    float *d_xr, *d_wq, *d_wp, *d_o;
    cudaGetSymbolAddress((void**)&d_xr, g_xr);
    cudaGetSymbolAddress((void**)&d_wq, g_wq);
    cudaGetSymbolAddress((void**)&d_wp, g_wp);
    cudaGetSymbolAddress((void**)&d_o,  g_o);

    cudaFuncSetAttribute(attn_tc, cudaFuncAttributeMaxDynamicSharedMemorySize,
                         ATTN_SMEM);

    // one-time tf32 pre-rounding (single fused launch)
    round_all<<<12288, 256>>>(x, d_xr, w_qkv, d_wq, w_proj, d_wp);

    dim3 g1(NQKV / 128, MROWS / 128);   // (24, 64)
    gemm_tf32<<<g1, 256>>>(d_xr, d_wq, b_qkv, nullptr, NQKV, 0);

    dim3 g2(TT / 128, HH, BB);          // (16, 16, 4)
    attn_tc<<<g2, 256, ATTN_SMEM>>>();

    dim3 g3(CC / 128, MROWS / 128);     // (8, 64)
    gemm_tf32<<<g3, 256>>>(d_o, d_wp, b_proj, out, CC, 1);
}

// round 15
// speedup vs baseline: 1.6486x; 1.0310x over previous
#include <cuda_runtime.h>
#include <math.h>
#include <stdint.h>

#define BB 4
#define TT 2048
#define CC 1024
#define HH 16
#define DD 64
#define MROWS (BB*TT)     // 8192
#define NQKV  (3*CC)      // 3072

// Scratch (device globals — allocation-free per harness rules)
__device__ float g_q[BB*HH*TT*DD];   // tf32-rounded, pre-scaled by 0.125*log2(e)
__device__ float g_k[BB*HH*TT*DD];   // tf32-rounded
__device__ float g_v[BB*HH*TT*DD];   // tf32-rounded
__device__ float g_o[MROWS*CC];      // tf32-rounded attention output
__device__ float g_xr[MROWS*CC];     // tf32-rounded x
__device__ float g_wq[CC*NQKV];      // tf32-rounded w_qkv
__device__ float g_wp[CC*CC];        // tf32-rounded w_proj

__device__ __forceinline__ float to_tf32(float x) {
    float y;
    asm("cvt.rna.tf32.f32 %0, %1;" : "=f"(y) : "f"(x));
    return y;
}
__device__ __forceinline__ float ex2(float x) {
    float y;
    asm("ex2.approx.ftz.f32 %0, %1;" : "=f"(y) : "f"(x));
    return y;
}
__device__ __forceinline__ uint32_t sptr(const void* p) {
    return (uint32_t)__cvta_generic_to_shared(p);
}
__device__ __forceinline__ void cp16(uint32_t s, const void* g) {
    asm volatile("cp.async.cg.shared.global [%0], [%1], 16;\n" :: "r"(s), "l"(g));
}
__device__ __forceinline__ void cp_commit() {
    asm volatile("cp.async.commit_group;\n");
}
template<int N> __device__ __forceinline__ void cp_wait() {
    asm volatile("cp.async.wait_group %0;\n" :: "n"(N));
}

__device__ __forceinline__ void mma_tf32(float d[4], const float a[4], const float b[2]) {
    asm volatile(
        "mma.sync.aligned.m16n8k8.row.col.f32.tf32.tf32.f32 "
        "{%0,%1,%2,%3}, {%4,%5,%6,%7}, {%8,%9}, {%0,%1,%2,%3};\n"
        : "+f"(d[0]), "+f"(d[1]), "+f"(d[2]), "+f"(d[3])
        : "r"(__float_as_uint(a[0])), "r"(__float_as_uint(a[1])),
          "r"(__float_as_uint(a[2])), "r"(__float_as_uint(a[3])),
          "r"(__float_as_uint(b[0])), "r"(__float_as_uint(b[1])));
}

// ---------------------------------------------------------------------------
// One-time tf32 rounding, all three tensors in ONE launch.
// Segments (in 1024-float blocks): x 8192, w_qkv 3072, w_proj 1024.
// ---------------------------------------------------------------------------
__global__ __launch_bounds__(256) void round_all(
    const float* __restrict__ x,  float* __restrict__ dx,
    const float* __restrict__ wq, float* __restrict__ dwq,
    const float* __restrict__ wp, float* __restrict__ dwp)
{
    const int bid = blockIdx.x;
    const float* src;
    float* dst;
    size_t base;
    if (bid < 8192)      { src = x;  dst = dx;  base = bid; }
    else if (bid < 11264){ src = wq; dst = dwq; base = bid - 8192; }
    else                 { src = wp; dst = dwp; base = bid - 11264; }
    const size_t i = (base * 256 + threadIdx.x) * 4;
    float4 v = *(const float4*)(src + i);
    v.x = to_tf32(v.x); v.y = to_tf32(v.y);
    v.z = to_tf32(v.z); v.w = to_tf32(v.w);
    *(float4*)(dst + i) = v;
}

#define SPITCH 136   // gemm smem pitch (floats)

// ---------------------------------------------------------------------------
// tf32 mma.sync GEMM — register-staged BK=16 double-buffered pipeline
// (measured plateau config, R12). QKV epilogue q/k/v select hoisted to
// CTA level (s = n>>10 is constant within a 128-wide N tile).
// ---------------------------------------------------------------------------
__global__ __launch_bounds__(256, 2) void gemm_tf32(
    const float* __restrict__ A, const float* __restrict__ Bw,
    const float* __restrict__ bias, float* __restrict__ out,
    int N, int mode)
{
    __shared__ float As[2][16 * SPITCH];
    __shared__ float Bs[2][16 * SPITCH];

    const int tid  = threadIdx.x;
    const int lane = tid & 31;
    const int wid  = tid >> 5;
    const int g    = lane >> 2;
    const int t4   = lane & 3;
    const int warp_m = (wid >> 2) * 64;
    const int warp_n = (wid & 3) * 32;
    const int m0 = blockIdx.y * 128;
    const int n0 = blockIdx.x * 128;

    const int ar = tid >> 2;
    const int ak = (tid & 3) * 4;
    const int br = tid >> 4;
    const int bc = (tid & 15) * 4;

    float acc[4][4][4];
    #pragma unroll
    for (int i = 0; i < 4; i++)
        #pragma unroll
        for (int j = 0; j < 4; j++)
            #pragma unroll
            for (int r = 0; r < 4; r++) acc[i][j][r] = 0.f;

    float4 a_s[2], b_s[2];

    auto ldg_tile = [&](int k0) {
        a_s[0] = *(const float4*)(A + (size_t)(m0 + ar) * CC + k0 + ak);
        a_s[1] = *(const float4*)(A + (size_t)(m0 + ar + 64) * CC + k0 + ak);
        b_s[0] = *(const float4*)(Bw + (size_t)(k0 + br) * N + n0 + bc);
        b_s[1] = *(const float4*)(Bw + (size_t)(k0 + br) * N + n0 + bc + 64);
    };
    auto sts_tile = [&](int buf) {
        #pragma unroll
        for (int h = 0; h < 2; h++) {
            const int m = ar + h * 64;
            const float4 a4 = a_s[h];
            As[buf][(ak + 0) * SPITCH + m] = a4.x;
            As[buf][(ak + 1) * SPITCH + m] = a4.y;
            As[buf][(ak + 2) * SPITCH + m] = a4.z;
            As[buf][(ak + 3) * SPITCH + m] = a4.w;
        }
        #pragma unroll
        for (int h = 0; h < 2; h++)
            *(float4*)&Bs[buf][br * SPITCH + bc + h * 64] = b_s[h];
    };

    ldg_tile(0);
    sts_tile(0);
    __syncthreads();

    for (int k0 = 0; k0 < CC; k0 += 16) {
        const int buf = (k0 >> 4) & 1;
        const bool pf = (k0 + 16) < CC;
        if (pf) ldg_tile(k0 + 16);       // LDG latency hidden behind mmas

        #pragma unroll
        for (int ks = 0; ks < 2; ks++) {
            const int kb = ks * 8;
            float af[4][4], bf[4][2];
            #pragma unroll
            for (int mt = 0; mt < 4; mt++) {
                const int m = warp_m + mt * 16 + g;
                af[mt][0] = As[buf][(kb + t4) * SPITCH + m];
                af[mt][1] = As[buf][(kb + t4) * SPITCH + m + 8];
                af[mt][2] = As[buf][(kb + t4 + 4) * SPITCH + m];
                af[mt][3] = As[buf][(kb + t4 + 4) * SPITCH + m + 8];
            }
            #pragma unroll
            for (int nt = 0; nt < 4; nt++) {
                const int n = warp_n + nt * 8 + g;
                bf[nt][0] = Bs[buf][(kb + t4) * SPITCH + n];
                bf[nt][1] = Bs[buf][(kb + t4 + 4) * SPITCH + n];
            }
            #pragma unroll
            for (int mt = 0; mt < 4; mt++)
                #pragma unroll
                for (int nt = 0; nt < 4; nt++)
                    mma_tf32(acc[mt][nt], af[mt], bf[nt]);
        }

        if (pf) sts_tile(buf ^ 1);
        __syncthreads();
    }

    if (mode == 1) {
        #pragma unroll
        for (int mt = 0; mt < 4; mt++)
            #pragma unroll
            for (int half = 0; half < 2; half++) {
                const int m = m0 + warp_m + mt * 16 + g + half * 8;
                #pragma unroll
                for (int nt = 0; nt < 4; nt++) {
                    const int n = n0 + warp_n + nt * 8 + t4 * 2;
                    float v0 = acc[mt][nt][half * 2 + 0] + bias[n];
                    float v1 = acc[mt][nt][half * 2 + 1] + bias[n + 1];
                    *(float2*)(out + (size_t)m * CC + n) = make_float2(v0, v1);
                }
            }
    } else {
        // s = n >> 10 is constant across the whole 128-wide N tile
        const int s = n0 >> 10;                      // 0:q 1:k 2:v
        float* gdst = (s == 0) ? g_q : (s == 1) ? g_k : g_v;
        const float sc = (s == 0) ? 0.125f * 1.44269504f : 1.f;
        #pragma unroll
        for (int mt = 0; mt < 4; mt++)
            #pragma unroll
            for (int half = 0; half < 2; half++) {
                const int m = m0 + warp_m + mt * 16 + g + half * 8;
                const int bidx = m >> 11;
                const int t = m & (TT - 1);
                #pragma unroll
                for (int nt = 0; nt < 4; nt++) {
                    const int n = n0 + warp_n + nt * 8 + t4 * 2;
                    const int h = (n & 1023) >> 6;
                    const int d = n & 63;
                    float v0 = (acc[mt][nt][half * 2 + 0] + bias[n]) * sc;
                    float v1 = (acc[mt][nt][half * 2 + 1] + bias[n + 1]) * sc;
                    const size_t idx = (((size_t)(bidx * HH + h)) * TT + t) * DD + d;
                    *(float2*)(gdst + idx) = make_float2(to_tf32(v0), to_tf32(v1));
                }
            }
    }
}

// ---------------------------------------------------------------------------
// Tensor-core causal flash attention (VERBATIM R12, the 895us-measured
// config). 128-query CTA, 8 warps, K+V double-buffered, 1 sync + 1 wait per
// key tile, fixed-max softmax in 2^ domain, deferred row-sum, per-warp smem
// P routing, fully-masked warps skip the last diagonal tile.
// ---------------------------------------------------------------------------
#define KPK 68
#define KPV 72
#define PP  36
#define NW  8
#define ATTN_SMEM ((2*64*KPK + 2*64*KPV + NW*16*PP) * 4)   // 90112 B

__global__ __launch_bounds__(256, 2) void attn_tc()
{
    extern __shared__ __align__(16) float dsm[];
    float* Ks = dsm;                               // [2][64*KPK]
    float* Vs = dsm + 2 * 64 * KPK;                // [2][64*KPV]
    float* Ps = dsm + 2 * 64 * KPK + 2 * 64 * KPV; // [NW][16*PP]

    const int qt  = (int)gridDim.x - 1 - (int)blockIdx.x;  // heavy tiles first
    const int h   = blockIdx.y;
    const int b   = blockIdx.z;
    const int tid  = threadIdx.x;
    const int lane = tid & 31;
    const int w    = tid >> 5;           // 0..7
    const int g    = lane >> 2;
    const int t4   = lane & 3;

    const size_t head_off = ((size_t)(b * HH + h)) * TT * DD;
    const float* __restrict__ qb = g_q + head_off;
    const float* __restrict__ kb = g_k + head_off;
    const float* __restrict__ vb = g_v + head_off;

    const int srow = tid >> 2;           // 0..63
    const int scol = (tid & 3) * 16;

    auto issue_kv = [&](int jt, int buf) {
        const float* ksrc = kb + (size_t)(jt * 64 + srow) * DD + scol;
        uint32_t kdst = sptr(&Ks[buf * 64 * KPK + srow * KPK + scol]);
        #pragma unroll
        for (int c = 0; c < 16; c += 4) cp16(kdst + c * 4, ksrc + c);
        const float* vsrc = vb + (size_t)(jt * 64 + srow) * DD + scol;
        uint32_t vdst = sptr(&Vs[buf * 64 * KPV + srow * KPV + scol]);
        #pragma unroll
        for (int c = 0; c < 16; c += 4) cp16(vdst + c * 4, vsrc + c);
        cp_commit();
    };

    float qf[8][4];
    {
        const int r0 = qt * 128 + w * 16 + g;
        #pragma unroll
        for (int kc = 0; kc < 8; kc++) {
            qf[kc][0] = qb[(size_t)r0 * DD + kc * 8 + t4];
            qf[kc][1] = qb[(size_t)(r0 + 8) * DD + kc * 8 + t4];
            qf[kc][2] = qb[(size_t)r0 * DD + kc * 8 + t4 + 4];
            qf[kc][3] = qb[(size_t)(r0 + 8) * DD + kc * 8 + t4 + 4];
        }
    }

    float o[8][4];
    #pragma unroll
    for (int nt = 0; nt < 8; nt++)
        #pragma unroll
        for (int r = 0; r < 4; r++) o[nt][r] = 0.f;
    float l0 = 0.f, l1 = 0.f;

    float* pb = Ps + w * 16 * PP;

    issue_kv(0, 0);

    const int njt = 2 * qt + 2;

    for (int jt = 0; jt < njt; jt++) {
        const int buf = jt & 1;

        cp_wait<0>();
        __syncthreads();
        if (jt + 1 < njt) issue_kv(jt + 1, buf ^ 1);

        const bool active = !(jt == 2 * qt + 1 && w < 4);
        if (active) {
            float s[8][4];
            #pragma unroll
            for (int nt = 0; nt < 8; nt++)
                #pragma unroll
                for (int r = 0; r < 4; r++) s[nt][r] = 0.f;

            const float* kbuf = Ks + buf * 64 * KPK;
            #pragma unroll
            for (int kc = 0; kc < 8; kc++) {
                #pragma unroll
                for (int nt = 0; nt < 8; nt++) {
                    float bk[2];
                    bk[0] = kbuf[(nt * 8 + g) * KPK + kc * 8 + t4];
                    bk[1] = kbuf[(nt * 8 + g) * KPK + kc * 8 + t4 + 4];
                    mma_tf32(s[nt], qf[kc], bk);
                }
            }

            if (jt >= 2 * qt) {
                const int rlo = w * 16 + g - (jt - 2 * qt) * 64;
                const int rhi = rlo + 8;
                #pragma unroll
                for (int nt = 0; nt < 8; nt++) {
                    const int col = nt * 8 + 2 * t4;
                    if (col     > rlo) s[nt][0] = -1e30f;
                    if (col + 1 > rlo) s[nt][1] = -1e30f;
                    if (col     > rhi) s[nt][2] = -1e30f;
                    if (col + 1 > rhi) s[nt][3] = -1e30f;
                }
            }

            #pragma unroll
            for (int nt = 0; nt < 8; nt++) {
                s[nt][0] = ex2(s[nt][0]);
                s[nt][1] = ex2(s[nt][1]);
                s[nt][2] = ex2(s[nt][2]);
                s[nt][3] = ex2(s[nt][3]);
                l0 += s[nt][0] + s[nt][1];
                l1 += s[nt][2] + s[nt][3];
            }

            const float* vbuf = Vs + buf * 64 * KPV;
            #pragma unroll
            for (int half = 0; half < 2; half++) {
                #pragma unroll
                for (int q = 0; q < 4; q++) {
                    const int nt = half * 4 + q;
                    const int col = q * 8 + 2 * t4;
                    *(float2*)&pb[g * PP + col] =
                        make_float2(to_tf32(s[nt][0]), to_tf32(s[nt][1]));
                    *(float2*)&pb[(g + 8) * PP + col] =
                        make_float2(to_tf32(s[nt][2]), to_tf32(s[nt][3]));
                }
                __syncwarp();
                #pragma unroll
                for (int kc2 = 0; kc2 < 4; kc2++) {
                    const int kc = half * 4 + kc2;
                    float a[4];
                    a[0] = pb[g * PP + kc2 * 8 + t4];
                    a[1] = pb[(g + 8) * PP + kc2 * 8 + t4];
                    a[2] = pb[g * PP + kc2 * 8 + t4 + 4];
                    a[3] = pb[(g + 8) * PP + kc2 * 8 + t4 + 4];
                    #pragma unroll
                    for (int nt = 0; nt < 8; nt++) {
                        float bv[2];
                        bv[0] = vbuf[(kc * 8 + t4) * KPV + nt * 8 + g];
                        bv[1] = vbuf[(kc * 8 + t4 + 4) * KPV + nt * 8 + g];
                        mma_tf32(o[nt], a, bv);
                    }
                }
                __syncwarp();
            }
        }
    }

    l0 += __shfl_xor_sync(0xffffffffu, l0, 1);
    l0 += __shfl_xor_sync(0xffffffffu, l0, 2);
    l1 += __shfl_xor_sync(0xffffffffu, l1, 1);
    l1 += __shfl_xor_sync(0xffffffffu, l1, 2);
    const float i0 = 1.f / l0;
    const float i1 = 1.f / l1;
    const int qrow = qt * 128 + w * 16;
    float* ob = g_o + ((size_t)(b * TT) + qrow) * CC + h * DD;
    #pragma unroll
    for (int nt = 0; nt < 8; nt++) {
        const int d = nt * 8 + 2 * t4;
        *(float2*)(ob + (size_t)g * CC + d) =
            make_float2(to_tf32(o[nt][0] * i0), to_tf32(o[nt][1] * i0));
        *(float2*)(ob + (size_t)(g + 8) * CC + d) =
            make_float2(to_tf32(o[nt][2] * i1), to_tf32(o[nt][3] * i1));
    }
}

extern "C" void kernel_launch(void* const* d_in, const int* in_sizes, int n_in,
                              void* d_out, int out_size)
{
    const float* x      = (const float*)d_in[0];
    const float* w_qkv  = (const float*)d_in[1];
    const float* b_qkv  = (const float*)d_in[2];
    const float* w_proj = (const float*)d_in[3];
    const float* b_proj = (const float*)d_in[4];
    float* out = (float*)d_out;

    float *d_xr, *d_wq, *d_wp, *d_o;
    cudaGetSymbolAddress((void**)&d_xr, g_xr);
    cudaGetSymbolAddress((void**)&d_wq, g_wq);
    cudaGetSymbolAddress((void**)&d_wp, g_wp);
    cudaGetSymbolAddress((void**)&d_o,  g_o);

    cudaFuncSetAttribute(attn_tc, cudaFuncAttributeMaxDynamicSharedMemorySize,
                         ATTN_SMEM);

    // one-time tf32 pre-rounding (single fused launch)
    round_all<<<12288, 256>>>(x, d_xr, w_qkv, d_wq, w_proj, d_wp);

    dim3 g1(NQKV / 128, MROWS / 128);   // (24, 64)
    gemm_tf32<<<g1, 256>>>(d_xr, d_wq, b_qkv, nullptr, NQKV, 0);

    dim3 g2(TT / 128, HH, BB);          // (16, 16, 4)
    attn_tc<<<g2, 256, ATTN_SMEM>>>();

    dim3 g3(CC / 128, MROWS / 128);     // (8, 64)
    gemm_tf32<<<g3, 256>>>(d_o, d_wp, b_proj, out, CC, 1);
}

// round 16
// speedup vs baseline: 1.6667x; 1.0110x over previous
#include <cuda_runtime.h>
#include <math.h>
#include <stdint.h>

#define BB 4
#define TT 2048
#define CC 1024
#define HH 16
#define DD 64
#define MROWS (BB*TT)     // 8192
#define NQKV  (3*CC)      // 3072

// Scratch (device globals — allocation-free per harness rules)
__device__ float g_q[BB*HH*TT*DD];   // tf32-rounded, pre-scaled by 0.125*log2(e)
__device__ float g_k[BB*HH*TT*DD];   // tf32-rounded
__device__ float g_v[BB*HH*TT*DD];   // tf32-rounded
__device__ float g_o[MROWS*CC];      // tf32-rounded attention output
__device__ float g_xr[MROWS*CC];     // tf32-rounded x
__device__ float g_wq[CC*NQKV];      // tf32-rounded w_qkv
__device__ float g_wp[CC*CC];        // tf32-rounded w_proj

__device__ __forceinline__ float to_tf32(float x) {
    float y;
    asm("cvt.rna.tf32.f32 %0, %1;" : "=f"(y) : "f"(x));
    return y;
}
__device__ __forceinline__ float ex2(float x) {
    float y;
    asm("ex2.approx.ftz.f32 %0, %1;" : "=f"(y) : "f"(x));
    return y;
}
__device__ __forceinline__ uint32_t sptr(const void* p) {
    return (uint32_t)__cvta_generic_to_shared(p);
}
__device__ __forceinline__ void cp16(uint32_t s, const void* g) {
    asm volatile("cp.async.cg.shared.global [%0], [%1], 16;\n" :: "r"(s), "l"(g));
}
__device__ __forceinline__ void cp_commit() {
    asm volatile("cp.async.commit_group;\n");
}
template<int N> __device__ __forceinline__ void cp_wait() {
    asm volatile("cp.async.wait_group %0;\n" :: "n"(N));
}

__device__ __forceinline__ void mma_tf32(float d[4], const float a[4], const float b[2]) {
    asm volatile(
        "mma.sync.aligned.m16n8k8.row.col.f32.tf32.tf32.f32 "
        "{%0,%1,%2,%3}, {%4,%5,%6,%7}, {%8,%9}, {%0,%1,%2,%3};\n"
        : "+f"(d[0]), "+f"(d[1]), "+f"(d[2]), "+f"(d[3])
        : "r"(__float_as_uint(a[0])), "r"(__float_as_uint(a[1])),
          "r"(__float_as_uint(a[2])), "r"(__float_as_uint(a[3])),
          "r"(__float_as_uint(b[0])), "r"(__float_as_uint(b[1])));
}

// ---------------------------------------------------------------------------
// One-time tf32 rounding, all three tensors in ONE launch.
// Segments (in 1024-float blocks): x 8192, w_qkv 3072, w_proj 1024.
// ---------------------------------------------------------------------------
__global__ __launch_bounds__(256) void round_all(
    const float* __restrict__ x,  float* __restrict__ dx,
    const float* __restrict__ wq, float* __restrict__ dwq,
    const float* __restrict__ wp, float* __restrict__ dwp)
{
    const int bid = blockIdx.x;
    const float* src;
    float* dst;
    size_t base;
    if (bid < 8192)      { src = x;  dst = dx;  base = bid; }
    else if (bid < 11264){ src = wq; dst = dwq; base = bid - 8192; }
    else                 { src = wp; dst = dwp; base = bid - 11264; }
    const size_t i = (base * 256 + threadIdx.x) * 4;
    float4 v = *(const float4*)(src + i);
    v.x = to_tf32(v.x); v.y = to_tf32(v.y);
    v.z = to_tf32(v.z); v.w = to_tf32(v.w);
    *(float4*)(dst + i) = v;
}

#define SPITCH 136   // gemm smem pitch (floats)

// ---------------------------------------------------------------------------
// tf32 mma.sync GEMM — register-staged BK=16 double-buffered pipeline with
// A k-row swizzle sigma(r) = (r & ~3) | ((r + (r>>2)) & 3):
//   A stores: bank = 8*((j+aq)&3) + ar  -> conflict-free (was 4-way!)
//   A loads:  rows {t4, 4+((t4+1)&3), 8+((t4+2)&3), 12+((t4+3)&3)},
//             bank = 8*(row&3)+g       -> still conflict-free
// Pure index permutation; numerics identical.
// Block 128x128, 8 warps (2x4), warp tile 64x32.
// mode 0: QKV epilogue (scatter tf32-rounded to g_q/g_k/g_v, select hoisted)
// mode 1: proj epilogue (write fp32 to out)
// ---------------------------------------------------------------------------
__global__ __launch_bounds__(256, 2) void gemm_tf32(
    const float* __restrict__ A, const float* __restrict__ Bw,
    const float* __restrict__ bias, float* __restrict__ out,
    int N, int mode)
{
    __shared__ float As[2][16 * SPITCH];
    __shared__ float Bs[2][16 * SPITCH];

    const int tid  = threadIdx.x;
    const int lane = tid & 31;
    const int wid  = tid >> 5;
    const int g    = lane >> 2;
    const int t4   = lane & 3;
    const int warp_m = (wid >> 2) * 64;
    const int warp_n = (wid & 3) * 32;
    const int m0 = blockIdx.y * 128;
    const int n0 = blockIdx.x * 128;

    const int ar = tid >> 2;
    const int aq = tid & 3;           // k-block index
    const int ak = aq * 4;            // gmem k offset (float4)
    const int br = tid >> 4;
    const int bc = (tid & 15) * 4;

    // sigma-swizzled A store rows for components x,y,z,w
    const int sr0 = ak + ( aq      & 3);
    const int sr1 = ak + ((aq + 1) & 3);
    const int sr2 = ak + ((aq + 2) & 3);
    const int sr3 = ak + ((aq + 3) & 3);

    // sigma-swizzled A load rows per ks slice
    const int lr00 = t4;                    // ks=0, k=t4
    const int lr01 = 4  + ((t4 + 1) & 3);   // ks=0, k=t4+4
    const int lr10 = 8  + ((t4 + 2) & 3);   // ks=1, k=8+t4
    const int lr11 = 12 + ((t4 + 3) & 3);   // ks=1, k=12+t4

    float acc[4][4][4];
    #pragma unroll
    for (int i = 0; i < 4; i++)
        #pragma unroll
        for (int j = 0; j < 4; j++)
            #pragma unroll
            for (int r = 0; r < 4; r++) acc[i][j][r] = 0.f;

    float4 a_s[2], b_s[2];

    auto ldg_tile = [&](int k0) {
        a_s[0] = *(const float4*)(A + (size_t)(m0 + ar) * CC + k0 + ak);
        a_s[1] = *(const float4*)(A + (size_t)(m0 + ar + 64) * CC + k0 + ak);
        b_s[0] = *(const float4*)(Bw + (size_t)(k0 + br) * N + n0 + bc);
        b_s[1] = *(const float4*)(Bw + (size_t)(k0 + br) * N + n0 + bc + 64);
    };
    auto sts_tile = [&](int buf) {
        #pragma unroll
        for (int h = 0; h < 2; h++) {
            const int m = ar + h * 64;
            const float4 a4 = a_s[h];
            As[buf][sr0 * SPITCH + m] = a4.x;
            As[buf][sr1 * SPITCH + m] = a4.y;
            As[buf][sr2 * SPITCH + m] = a4.z;
            As[buf][sr3 * SPITCH + m] = a4.w;
        }
        #pragma unroll
        for (int h = 0; h < 2; h++)
            *(float4*)&Bs[buf][br * SPITCH + bc + h * 64] = b_s[h];
    };

    ldg_tile(0);
    sts_tile(0);
    __syncthreads();

    for (int k0 = 0; k0 < CC; k0 += 16) {
        const int buf = (k0 >> 4) & 1;
        const bool pf = (k0 + 16) < CC;
        if (pf) ldg_tile(k0 + 16);       // LDG latency hidden behind mmas

        #pragma unroll
        for (int ks = 0; ks < 2; ks++) {
            const int kb = ks * 8;
            const int rA = (ks == 0) ? lr00 : lr10;   // sigma(kb+t4)
            const int rB = (ks == 0) ? lr01 : lr11;   // sigma(kb+t4+4)
            float af[4][4], bf[4][2];
            #pragma unroll
            for (int mt = 0; mt < 4; mt++) {
                const int m = warp_m + mt * 16 + g;
                af[mt][0] = As[buf][rA * SPITCH + m];
                af[mt][1] = As[buf][rA * SPITCH + m + 8];
                af[mt][2] = As[buf][rB * SPITCH + m];
                af[mt][3] = As[buf][rB * SPITCH + m + 8];
            }
            #pragma unroll
            for (int nt = 0; nt < 4; nt++) {
                const int n = warp_n + nt * 8 + g;
                bf[nt][0] = Bs[buf][(kb + t4) * SPITCH + n];
                bf[nt][1] = Bs[buf][(kb + t4 + 4) * SPITCH + n];
            }
            #pragma unroll
            for (int mt = 0; mt < 4; mt++)
                #pragma unroll
                for (int nt = 0; nt < 4; nt++)
                    mma_tf32(acc[mt][nt], af[mt], bf[nt]);
        }

        if (pf) sts_tile(buf ^ 1);
        __syncthreads();
    }

    if (mode == 1) {
        #pragma unroll
        for (int mt = 0; mt < 4; mt++)
            #pragma unroll
            for (int half = 0; half < 2; half++) {
                const int m = m0 + warp_m + mt * 16 + g + half * 8;
                #pragma unroll
                for (int nt = 0; nt < 4; nt++) {
                    const int n = n0 + warp_n + nt * 8 + t4 * 2;
                    float v0 = acc[mt][nt][half * 2 + 0] + bias[n];
                    float v1 = acc[mt][nt][half * 2 + 1] + bias[n + 1];
                    *(float2*)(out + (size_t)m * CC + n) = make_float2(v0, v1);
                }
            }
    } else {
        // s = n >> 10 is constant across the whole 128-wide N tile
        const int s = n0 >> 10;                      // 0:q 1:k 2:v
        float* gdst = (s == 0) ? g_q : (s == 1) ? g_k : g_v;
        const float sc = (s == 0) ? 0.125f * 1.44269504f : 1.f;
        #pragma unroll
        for (int mt = 0; mt < 4; mt++)
            #pragma unroll
            for (int half = 0; half < 2; half++) {
                const int m = m0 + warp_m + mt * 16 + g + half * 8;
                const int bidx = m >> 11;
                const int t = m & (TT - 1);
                #pragma unroll
                for (int nt = 0; nt < 4; nt++) {
                    const int n = n0 + warp_n + nt * 8 + t4 * 2;
                    const int h = (n & 1023) >> 6;
                    const int d = n & 63;
                    float v0 = (acc[mt][nt][half * 2 + 0] + bias[n]) * sc;
                    float v1 = (acc[mt][nt][half * 2 + 1] + bias[n + 1]) * sc;
                    const size_t idx = (((size_t)(bidx * HH + h)) * TT + t) * DD + d;
                    *(float2*)(gdst + idx) = make_float2(to_tf32(v0), to_tf32(v1));
                }
            }
    }
}

// ---------------------------------------------------------------------------
// Tensor-core causal flash attention (VERBATIM best-measured config).
// 128-query CTA, 8 warps, K+V double-buffered, 1 sync + 1 wait per key tile,
// fixed-max softmax in 2^ domain, deferred row-sum, per-warp smem P routing,
// fully-masked warps skip the last diagonal tile.
// ---------------------------------------------------------------------------
#define KPK 68
#define KPV 72
#define PP  36
#define NW  8
#define ATTN_SMEM ((2*64*KPK + 2*64*KPV + NW*16*PP) * 4)   // 90112 B

__global__ __launch_bounds__(256, 2) void attn_tc()
{
    extern __shared__ __align__(16) float dsm[];
    float* Ks = dsm;                               // [2][64*KPK]
    float* Vs = dsm + 2 * 64 * KPK;                // [2][64*KPV]
    float* Ps = dsm + 2 * 64 * KPK + 2 * 64 * KPV; // [NW][16*PP]

    const int qt  = (int)gridDim.x - 1 - (int)blockIdx.x;  // heavy tiles first
    const int h   = blockIdx.y;
    const int b   = blockIdx.z;
    const int tid  = threadIdx.x;
    const int lane = tid & 31;
    const int w    = tid >> 5;           // 0..7
    const int g    = lane >> 2;
    const int t4   = lane & 3;

    const size_t head_off = ((size_t)(b * HH + h)) * TT * DD;
    const float* __restrict__ qb = g_q + head_off;
    const float* __restrict__ kb = g_k + head_off;
    const float* __restrict__ vb = g_v + head_off;

    const int srow = tid >> 2;           // 0..63
    const int scol = (tid & 3) * 16;

    auto issue_kv = [&](int jt, int buf) {
        const float* ksrc = kb + (size_t)(jt * 64 + srow) * DD + scol;
        uint32_t kdst = sptr(&Ks[buf * 64 * KPK + srow * KPK + scol]);
        #pragma unroll
        for (int c = 0; c < 16; c += 4) cp16(kdst + c * 4, ksrc + c);
        const float* vsrc = vb + (size_t)(jt * 64 + srow) * DD + scol;
        uint32_t vdst = sptr(&Vs[buf * 64 * KPV + srow * KPV + scol]);
        #pragma unroll
        for (int c = 0; c < 16; c += 4) cp16(vdst + c * 4, vsrc + c);
        cp_commit();
    };

    float qf[8][4];
    {
        const int r0 = qt * 128 + w * 16 + g;
        #pragma unroll
        for (int kc = 0; kc < 8; kc++) {
            qf[kc][0] = qb[(size_t)r0 * DD + kc * 8 + t4];
            qf[kc][1] = qb[(size_t)(r0 + 8) * DD + kc * 8 + t4];
            qf[kc][2] = qb[(size_t)r0 * DD + kc * 8 + t4 + 4];
            qf[kc][3] = qb[(size_t)(r0 + 8) * DD + kc * 8 + t4 + 4];
        }
    }

    float o[8][4];
    #pragma unroll
    for (int nt = 0; nt < 8; nt++)
        #pragma unroll
        for (int r = 0; r < 4; r++) o[nt][r] = 0.f;
    float l0 = 0.f, l1 = 0.f;

    float* pb = Ps + w * 16 * PP;

    issue_kv(0, 0);

    const int njt = 2 * qt + 2;

    for (int jt = 0; jt < njt; jt++) {
        const int buf = jt & 1;

        cp_wait<0>();
        __syncthreads();
        if (jt + 1 < njt) issue_kv(jt + 1, buf ^ 1);

        const bool active = !(jt == 2 * qt + 1 && w < 4);
        if (active) {
            float s[8][4];
            #pragma unroll
            for (int nt = 0; nt < 8; nt++)
                #pragma unroll
                for (int r = 0; r < 4; r++) s[nt][r] = 0.f;

            const float* kbuf = Ks + buf * 64 * KPK;
            #pragma unroll
            for (int kc = 0; kc < 8; kc++) {
                #pragma unroll
                for (int nt = 0; nt < 8; nt++) {
                    float bk[2];
                    bk[0] = kbuf[(nt * 8 + g) * KPK + kc * 8 + t4];
                    bk[1] = kbuf[(nt * 8 + g) * KPK + kc * 8 + t4 + 4];
                    mma_tf32(s[nt], qf[kc], bk);
                }
            }

            if (jt >= 2 * qt) {
                const int rlo = w * 16 + g - (jt - 2 * qt) * 64;
                const int rhi = rlo + 8;
                #pragma unroll
                for (int nt = 0; nt < 8; nt++) {
                    const int col = nt * 8 + 2 * t4;
                    if (col     > rlo) s[nt][0] = -1e30f;
                    if (col + 1 > rlo) s[nt][1] = -1e30f;
                    if (col     > rhi) s[nt][2] = -1e30f;
                    if (col + 1 > rhi) s[nt][3] = -1e30f;
                }
            }

            #pragma unroll
            for (int nt = 0; nt < 8; nt++) {
                s[nt][0] = ex2(s[nt][0]);
                s[nt][1] = ex2(s[nt][1]);
                s[nt][2] = ex2(s[nt][2]);
                s[nt][3] = ex2(s[nt][3]);
                l0 += s[nt][0] + s[nt][1];
                l1 += s[nt][2] + s[nt][3];
            }

            const float* vbuf = Vs + buf * 64 * KPV;
            #pragma unroll
            for (int half = 0; half < 2; half++) {
                #pragma unroll
                for (int q = 0; q < 4; q++) {
                    const int nt = half * 4 + q;
                    const int col = q * 8 + 2 * t4;
                    *(float2*)&pb[g * PP + col] =
                        make_float2(to_tf32(s[nt][0]), to_tf32(s[nt][1]));
                    *(float2*)&pb[(g + 8) * PP + col] =
                        make_float2(to_tf32(s[nt][2]), to_tf32(s[nt][3]));
                }
                __syncwarp();
                #pragma unroll
                for (int kc2 = 0; kc2 < 4; kc2++) {
                    const int kc = half * 4 + kc2;
                    float a[4];
                    a[0] = pb[g * PP + kc2 * 8 + t4];
                    a[1] = pb[(g + 8) * PP + kc2 * 8 + t4];
                    a[2] = pb[g * PP + kc2 * 8 + t4 + 4];
                    a[3] = pb[(g + 8) * PP + kc2 * 8 + t4 + 4];
                    #pragma unroll
                    for (int nt = 0; nt < 8; nt++) {
                        float bv[2];
                        bv[0] = vbuf[(kc * 8 + t4) * KPV + nt * 8 + g];
                        bv[1] = vbuf[(kc * 8 + t4 + 4) * KPV + nt * 8 + g];
                        mma_tf32(o[nt], a, bv);
                    }
                }
                __syncwarp();
            }
        }
    }

    l0 += __shfl_xor_sync(0xffffffffu, l0, 1);
    l0 += __shfl_xor_sync(0xffffffffu, l0, 2);
    l1 += __shfl_xor_sync(0xffffffffu, l1, 1);
    l1 += __shfl_xor_sync(0xffffffffu, l1, 2);
    const float i0 = 1.f / l0;
    const float i1 = 1.f / l1;
    const int qrow = qt * 128 + w * 16;
    float* ob = g_o + ((size_t)(b * TT) + qrow) * CC + h * DD;
    #pragma unroll
    for (int nt = 0; nt < 8; nt++) {
        const int d = nt * 8 + 2 * t4;
        *(float2*)(ob + (size_t)g * CC + d) =
            make_float2(to_tf32(o[nt][0] * i0), to_tf32(o[nt][1] * i0));
        *(float2*)(ob + (size_t)(g + 8) * CC + d) =
            make_float2(to_tf32(o[nt][2] * i1), to_tf32(o[nt][3] * i1));
    }
}

extern "C" void kernel_launch(void* const* d_in, const int* in_sizes, int n_in,
                              void* d_out, int out_size)
{
    const float* x      = (const float*)d_in[0];
    const float* w_qkv  = (const float*)d_in[1];
    const float* b_qkv  = (const float*)d_in[2];
    const float* w_proj = (const float*)d_in[3];
    const float* b_proj = (const float*)d_in[4];
    float* out = (float*)d_out;

    float *d_xr, *d_wq, *d_wp, *d_o;
    cudaGetSymbolAddress((void**)&d_xr, g_xr);
    cudaGetSymbolAddress((void**)&d_wq, g_wq);
    cudaGetSymbolAddress((void**)&d_wp, g_wp);
    cudaGetSymbolAddress((void**)&d_o,  g_o);

    cudaFuncSetAttribute(attn_tc, cudaFuncAttributeMaxDynamicSharedMemorySize,
                         ATTN_SMEM);

    // one-time tf32 pre-rounding (single fused launch)
    round_all<<<12288, 256>>>(x, d_xr, w_qkv, d_wq, w_proj, d_wp);

    dim3 g1(NQKV / 128, MROWS / 128);   // (24, 64)
    gemm_tf32<<<g1, 256>>>(d_xr, d_wq, b_qkv, nullptr, NQKV, 0);

    dim3 g2(TT / 128, HH, BB);          // (16, 16, 4)
    attn_tc<<<g2, 256, ATTN_SMEM>>>();

    dim3 g3(CC / 128, MROWS / 128);     // (8, 64)
    gemm_tf32<<<g3, 256>>>(d_o, d_wp, b_proj, out, CC, 1);
}

// round 17
// speedup vs baseline: 1.7764x; 1.0658x over previous
#include <cuda_runtime.h>
#include <math.h>
#include <stdint.h>

#define BB 4
#define TT 2048
#define CC 1024
#define HH 16
#define DD 64
#define MROWS (BB*TT)     // 8192
#define NQKV  (3*CC)      // 3072

// Scratch (device globals — allocation-free per harness rules)
// g_k / g_v are FRAGMENT-ORDERED per 64x64 tile (see epilogue for mapping).
__device__ float g_q[BB*HH*TT*DD];   // row-major, tf32-rounded, pre-scaled
__device__ float g_k[BB*HH*TT*DD];   // fragment-ordered, tf32-rounded
__device__ float g_v[BB*HH*TT*DD];   // fragment-ordered, tf32-rounded
__device__ float g_o[MROWS*CC];      // tf32-rounded attention output
__device__ float g_xr[MROWS*CC];     // tf32-rounded x
__device__ float g_wq[CC*NQKV];      // tf32-rounded w_qkv
__device__ float g_wp[CC*CC];        // tf32-rounded w_proj

__device__ __forceinline__ float to_tf32(float x) {
    float y;
    asm("cvt.rna.tf32.f32 %0, %1;" : "=f"(y) : "f"(x));
    return y;
}
__device__ __forceinline__ float ex2(float x) {
    float y;
    asm("ex2.approx.ftz.f32 %0, %1;" : "=f"(y) : "f"(x));
    return y;
}
__device__ __forceinline__ uint32_t sptr(const void* p) {
    return (uint32_t)__cvta_generic_to_shared(p);
}
__device__ __forceinline__ void cp16(uint32_t s, const void* g) {
    asm volatile("cp.async.cg.shared.global [%0], [%1], 16;\n" :: "r"(s), "l"(g));
}
__device__ __forceinline__ void cp_commit() {
    asm volatile("cp.async.commit_group;\n");
}
template<int N> __device__ __forceinline__ void cp_wait() {
    asm volatile("cp.async.wait_group %0;\n" :: "n"(N));
}

__device__ __forceinline__ void mma_tf32(float d[4], const float a[4], const float b[2]) {
    asm volatile(
        "mma.sync.aligned.m16n8k8.row.col.f32.tf32.tf32.f32 "
        "{%0,%1,%2,%3}, {%4,%5,%6,%7}, {%8,%9}, {%0,%1,%2,%3};\n"
        : "+f"(d[0]), "+f"(d[1]), "+f"(d[2]), "+f"(d[3])
        : "r"(__float_as_uint(a[0])), "r"(__float_as_uint(a[1])),
          "r"(__float_as_uint(a[2])), "r"(__float_as_uint(a[3])),
          "r"(__float_as_uint(b[0])), "r"(__float_as_uint(b[1])));
}

// ---------------------------------------------------------------------------
// One-time tf32 rounding, all three tensors in ONE launch.
// ---------------------------------------------------------------------------
__global__ __launch_bounds__(256) void round_all(
    const float* __restrict__ x,  float* __restrict__ dx,
    const float* __restrict__ wq, float* __restrict__ dwq,
    const float* __restrict__ wp, float* __restrict__ dwp)
{
    const int bid = blockIdx.x;
    const float* src;
    float* dst;
    size_t base;
    if (bid < 8192)      { src = x;  dst = dx;  base = bid; }
    else if (bid < 11264){ src = wq; dst = dwq; base = bid - 8192; }
    else                 { src = wp; dst = dwp; base = bid - 11264; }
    const size_t i = (base * 256 + threadIdx.x) * 4;
    float4 v = *(const float4*)(src + i);
    v.x = to_tf32(v.x); v.y = to_tf32(v.y);
    v.z = to_tf32(v.z); v.w = to_tf32(v.w);
    *(float4*)(dst + i) = v;
}

#define SPITCH 136   // gemm smem pitch (floats)

// ---------------------------------------------------------------------------
// tf32 mma.sync GEMM — register-staged BK=16 double-buffered pipeline with
// the R16 A k-row swizzle (conflict-free stores AND loads).
// mode 0: QKV epilogue. q -> row-major g_q (scaled); k/v -> FRAGMENT-ORDERED
//   g_k/g_v: per 64x64 (key,dim) tile, element (kc*8+nt)*64 + lane*2 + slot:
//   K: lane=4*(key&7)+(d&3), slot=(d>>2)&1, kc=d>>3,  nt=key>>3
//   V: lane=4*(d&7)+(key&3), slot=(key>>2)&1, kc=key>>3, nt=d>>3
// mode 1: proj epilogue (write fp32 to out)
// ---------------------------------------------------------------------------
__global__ __launch_bounds__(256, 2) void gemm_tf32(
    const float* __restrict__ A, const float* __restrict__ Bw,
    const float* __restrict__ bias, float* __restrict__ out,
    int N, int mode)
{
    __shared__ float As[2][16 * SPITCH];
    __shared__ float Bs[2][16 * SPITCH];

    const int tid  = threadIdx.x;
    const int lane = tid & 31;
    const int wid  = tid >> 5;
    const int g    = lane >> 2;
    const int t4   = lane & 3;
    const int warp_m = (wid >> 2) * 64;
    const int warp_n = (wid & 3) * 32;
    const int m0 = blockIdx.y * 128;
    const int n0 = blockIdx.x * 128;

    const int ar = tid >> 2;
    const int aq = tid & 3;
    const int ak = aq * 4;
    const int br = tid >> 4;
    const int bc = (tid & 15) * 4;

    const int sr0 = ak + ( aq      & 3);
    const int sr1 = ak + ((aq + 1) & 3);
    const int sr2 = ak + ((aq + 2) & 3);
    const int sr3 = ak + ((aq + 3) & 3);

    const int lr00 = t4;
    const int lr01 = 4  + ((t4 + 1) & 3);
    const int lr10 = 8  + ((t4 + 2) & 3);
    const int lr11 = 12 + ((t4 + 3) & 3);

    float acc[4][4][4];
    #pragma unroll
    for (int i = 0; i < 4; i++)
        #pragma unroll
        for (int j = 0; j < 4; j++)
            #pragma unroll
            for (int r = 0; r < 4; r++) acc[i][j][r] = 0.f;

    float4 a_s[2], b_s[2];

    auto ldg_tile = [&](int k0) {
        a_s[0] = *(const float4*)(A + (size_t)(m0 + ar) * CC + k0 + ak);
        a_s[1] = *(const float4*)(A + (size_t)(m0 + ar + 64) * CC + k0 + ak);
        b_s[0] = *(const float4*)(Bw + (size_t)(k0 + br) * N + n0 + bc);
        b_s[1] = *(const float4*)(Bw + (size_t)(k0 + br) * N + n0 + bc + 64);
    };
    auto sts_tile = [&](int buf) {
        #pragma unroll
        for (int h = 0; h < 2; h++) {
            const int m = ar + h * 64;
            const float4 a4 = a_s[h];
            As[buf][sr0 * SPITCH + m] = a4.x;
            As[buf][sr1 * SPITCH + m] = a4.y;
            As[buf][sr2 * SPITCH + m] = a4.z;
            As[buf][sr3 * SPITCH + m] = a4.w;
        }
        #pragma unroll
        for (int h = 0; h < 2; h++)
            *(float4*)&Bs[buf][br * SPITCH + bc + h * 64] = b_s[h];
    };

    ldg_tile(0);
    sts_tile(0);
    __syncthreads();

    for (int k0 = 0; k0 < CC; k0 += 16) {
        const int buf = (k0 >> 4) & 1;
        const bool pf = (k0 + 16) < CC;
        if (pf) ldg_tile(k0 + 16);

        #pragma unroll
        for (int ks = 0; ks < 2; ks++) {
            const int kb = ks * 8;
            const int rA = (ks == 0) ? lr00 : lr10;
            const int rB = (ks == 0) ? lr01 : lr11;
            float af[4][4], bf[4][2];
            #pragma unroll
            for (int mt = 0; mt < 4; mt++) {
                const int m = warp_m + mt * 16 + g;
                af[mt][0] = As[buf][rA * SPITCH + m];
                af[mt][1] = As[buf][rA * SPITCH + m + 8];
                af[mt][2] = As[buf][rB * SPITCH + m];
                af[mt][3] = As[buf][rB * SPITCH + m + 8];
            }
            #pragma unroll
            for (int nt = 0; nt < 4; nt++) {
                const int n = warp_n + nt * 8 + g;
                bf[nt][0] = Bs[buf][(kb + t4) * SPITCH + n];
                bf[nt][1] = Bs[buf][(kb + t4 + 4) * SPITCH + n];
            }
            #pragma unroll
            for (int mt = 0; mt < 4; mt++)
                #pragma unroll
                for (int nt = 0; nt < 4; nt++)
                    mma_tf32(acc[mt][nt], af[mt], bf[nt]);
        }

        if (pf) sts_tile(buf ^ 1);
        __syncthreads();
    }

    if (mode == 1) {
        #pragma unroll
        for (int mt = 0; mt < 4; mt++)
            #pragma unroll
            for (int half = 0; half < 2; half++) {
                const int m = m0 + warp_m + mt * 16 + g + half * 8;
                #pragma unroll
                for (int nt = 0; nt < 4; nt++) {
                    const int n = n0 + warp_n + nt * 8 + t4 * 2;
                    float v0 = acc[mt][nt][half * 2 + 0] + bias[n];
                    float v1 = acc[mt][nt][half * 2 + 1] + bias[n + 1];
                    *(float2*)(out + (size_t)m * CC + n) = make_float2(v0, v1);
                }
            }
    } else {
        const int s = n0 >> 10;                      // 0:q 1:k 2:v (CTA-const)
        if (s == 0) {
            const float sc = 0.125f * 1.44269504f;
            #pragma unroll
            for (int mt = 0; mt < 4; mt++)
                #pragma unroll
                for (int half = 0; half < 2; half++) {
                    const int m = m0 + warp_m + mt * 16 + g + half * 8;
                    const int bidx = m >> 11;
                    const int t = m & (TT - 1);
                    #pragma unroll
                    for (int nt = 0; nt < 4; nt++) {
                        const int n = n0 + warp_n + nt * 8 + t4 * 2;
                        const int h = (n & 1023) >> 6;
                        const int d = n & 63;
                        float v0 = (acc[mt][nt][half * 2 + 0] + bias[n]) * sc;
                        float v1 = (acc[mt][nt][half * 2 + 1] + bias[n + 1]) * sc;
                        const size_t idx = (((size_t)(bidx * HH + h)) * TT + t) * DD + d;
                        *(float2*)(g_q + idx) = make_float2(to_tf32(v0), to_tf32(v1));
                    }
                }
        } else {
            float* gdst = (s == 1) ? g_k : g_v;
            #pragma unroll
            for (int mt = 0; mt < 4; mt++)
                #pragma unroll
                for (int half = 0; half < 2; half++) {
                    const int m = m0 + warp_m + mt * 16 + g + half * 8;
                    const int bidx = m >> 11;
                    const int t = m & (TT - 1);
                    const int key = t & 63;
                    const size_t tb = (size_t)(t >> 6) * 4096;
                    #pragma unroll
                    for (int nt = 0; nt < 4; nt++) {
                        const int n = n0 + warp_n + nt * 8 + t4 * 2;
                        const int h = (n & 1023) >> 6;
                        const int d = n & 63;      // even
                        float v0 = to_tf32(acc[mt][nt][half * 2 + 0] + bias[n]);
                        float v1 = to_tf32(acc[mt][nt][half * 2 + 1] + bias[n + 1]);
                        const size_t head = ((size_t)(bidx * HH + h)) * (TT * DD);
                        if (s == 1) {
                            // K: lane=4*(key&7)+(d&3), slot=(d>>2)&1
                            const int kc = d >> 3, pos = d & 7;
                            const int slot = pos >> 2, t4p = pos & 3;
                            const int ntf = key >> 3, gk = key & 7;
                            const int ln = gk * 4 + t4p;
                            const size_t idx = head + tb
                                + (size_t)((kc * 8 + ntf) * 64 + ln * 2 + slot);
                            gdst[idx]     = v0;
                            gdst[idx + 2] = v1;      // d+1: t4p+1 -> lane+1 -> +2
                        } else {
                            // V: lane=4*(d&7)+(key&3), slot=(key>>2)&1
                            const int kc = key >> 3, posk = key & 7;
                            const int slot = posk >> 2, t4p = posk & 3;
                            const int ntf = d >> 3, gv = d & 7;
                            const int ln = gv * 4 + t4p;
                            const size_t idx = head + tb
                                + (size_t)((kc * 8 + ntf) * 64 + ln * 2 + slot);
                            gdst[idx]     = v0;
                            gdst[idx + 8] = v1;      // d+1: g+1 -> lane+4 -> +8
                        }
                    }
                }
        }
    }
}

// ---------------------------------------------------------------------------
// Tensor-core causal flash attention with FRAGMENT-ORDERED K/V:
// each B-fragment is ONE lane-linear LDS.64 (256 LDS.32 -> 128 LDS.64/tile).
// Tiles staged linearly (4KB-aligned, no pitch/swizzle; cp.async coalesced).
// Otherwise identical to best-measured config: 128-query CTA, 8 warps,
// K+V double-buffered, 1 sync + 1 wait per tile, fixed-max 2^-softmax,
// deferred row-sum, per-warp smem P routing, last-diag warp skip.
// ---------------------------------------------------------------------------
#define PP  36
#define NW  8
#define ATTN_SMEM ((2*4096 + 2*4096 + NW*16*PP) * 4)   // 83968 B

__global__ __launch_bounds__(256, 2) void attn_tc()
{
    extern __shared__ __align__(16) float dsm[];
    float* Ks = dsm;                     // [2][4096]
    float* Vs = dsm + 2 * 4096;          // [2][4096]
    float* Ps = dsm + 4 * 4096;          // [NW][16*PP]

    const int qt  = (int)gridDim.x - 1 - (int)blockIdx.x;  // heavy tiles first
    const int h   = blockIdx.y;
    const int b   = blockIdx.z;
    const int tid  = threadIdx.x;
    const int lane = tid & 31;
    const int w    = tid >> 5;           // 0..7
    const int g    = lane >> 2;
    const int t4   = lane & 3;

    const size_t head_off = ((size_t)(b * HH + h)) * TT * DD;
    const float* __restrict__ qb = g_q + head_off;
    const float* __restrict__ kb = g_k + head_off;   // fragment-ordered tiles
    const float* __restrict__ vb = g_v + head_off;   // fragment-ordered tiles

    // linear staging: 4096 floats/tile, 16 floats (4 x cp16) per thread
    const int soff = tid * 16;

    auto issue_kv = [&](int jt, int buf) {
        const float* ksrc = kb + (size_t)jt * 4096 + soff;
        uint32_t kdst = sptr(&Ks[buf * 4096 + soff]);
        #pragma unroll
        for (int c = 0; c < 16; c += 4) cp16(kdst + c * 4, ksrc + c);
        const float* vsrc = vb + (size_t)jt * 4096 + soff;
        uint32_t vdst = sptr(&Vs[buf * 4096 + soff]);
        #pragma unroll
        for (int c = 0; c < 16; c += 4) cp16(vdst + c * 4, vsrc + c);
        cp_commit();
    };

    float qf[8][4];
    {
        const int r0 = qt * 128 + w * 16 + g;
        #pragma unroll
        for (int kc = 0; kc < 8; kc++) {
            qf[kc][0] = qb[(size_t)r0 * DD + kc * 8 + t4];
            qf[kc][1] = qb[(size_t)(r0 + 8) * DD + kc * 8 + t4];
            qf[kc][2] = qb[(size_t)r0 * DD + kc * 8 + t4 + 4];
            qf[kc][3] = qb[(size_t)(r0 + 8) * DD + kc * 8 + t4 + 4];
        }
    }

    float o[8][4];
    #pragma unroll
    for (int nt = 0; nt < 8; nt++)
        #pragma unroll
        for (int r = 0; r < 4; r++) o[nt][r] = 0.f;
    float l0 = 0.f, l1 = 0.f;

    float* pb = Ps + w * 16 * PP;

    issue_kv(0, 0);

    const int njt = 2 * qt + 2;

    for (int jt = 0; jt < njt; jt++) {
        const int buf = jt & 1;

        cp_wait<0>();
        __syncthreads();
        if (jt + 1 < njt) issue_kv(jt + 1, buf ^ 1);

        const bool active = !(jt == 2 * qt + 1 && w < 4);
        if (active) {
            float s[8][4];
            #pragma unroll
            for (int nt = 0; nt < 8; nt++)
                #pragma unroll
                for (int r = 0; r < 4; r++) s[nt][r] = 0.f;

            const float* kbuf = Ks + buf * 4096;
            #pragma unroll
            for (int kc = 0; kc < 8; kc++) {
                #pragma unroll
                for (int nt = 0; nt < 8; nt++) {
                    const float2 bk2 = *(const float2*)
                        &kbuf[((kc * 8 + nt) << 6) + lane * 2];
                    float bk[2] = {bk2.x, bk2.y};
                    mma_tf32(s[nt], qf[kc], bk);
                }
            }

            if (jt >= 2 * qt) {
                const int rlo = w * 16 + g - (jt - 2 * qt) * 64;
                const int rhi = rlo + 8;
                #pragma unroll
                for (int nt = 0; nt < 8; nt++) {
                    const int col = nt * 8 + 2 * t4;
                    if (col     > rlo) s[nt][0] = -1e30f;
                    if (col + 1 > rlo) s[nt][1] = -1e30f;
                    if (col     > rhi) s[nt][2] = -1e30f;
                    if (col + 1 > rhi) s[nt][3] = -1e30f;
                }
            }

            #pragma unroll
            for (int nt = 0; nt < 8; nt++) {
                s[nt][0] = ex2(s[nt][0]);
                s[nt][1] = ex2(s[nt][1]);
                s[nt][2] = ex2(s[nt][2]);
                s[nt][3] = ex2(s[nt][3]);
                l0 += s[nt][0] + s[nt][1];
                l1 += s[nt][2] + s[nt][3];
            }

            const float* vbuf = Vs + buf * 4096;
            #pragma unroll
            for (int half = 0; half < 2; half++) {
                #pragma unroll
                for (int q = 0; q < 4; q++) {
                    const int nt = half * 4 + q;
                    const int col = q * 8 + 2 * t4;
                    *(float2*)&pb[g * PP + col] =
                        make_float2(to_tf32(s[nt][0]), to_tf32(s[nt][1]));
                    *(float2*)&pb[(g + 8) * PP + col] =
                        make_float2(to_tf32(s[nt][2]), to_tf32(s[nt][3]));
                }
                __syncwarp();
                #pragma unroll
                for (int kc2 = 0; kc2 < 4; kc2++) {
                    const int kc = half * 4 + kc2;
                    float a[4];
                    a[0] = pb[g * PP + kc2 * 8 + t4];
                    a[1] = pb[(g + 8) * PP + kc2 * 8 + t4];
                    a[2] = pb[g * PP + kc2 * 8 + t4 + 4];
                    a[3] = pb[(g + 8) * PP + kc2 * 8 + t4 + 4];
                    #pragma unroll
                    for (int nt = 0; nt < 8; nt++) {
                        const float2 bv2 = *(const float2*)
                            &vbuf[((kc * 8 + nt) << 6) + lane * 2];
                        float bv[2] = {bv2.x, bv2.y};
                        mma_tf32(o[nt], a, bv);
                    }
                }
                __syncwarp();
            }
        }
    }

    l0 += __shfl_xor_sync(0xffffffffu, l0, 1);
    l0 += __shfl_xor_sync(0xffffffffu, l0, 2);
    l1 += __shfl_xor_sync(0xffffffffu, l1, 1);
    l1 += __shfl_xor_sync(0xffffffffu, l1, 2);
    const float i0 = 1.f / l0;
    const float i1 = 1.f / l1;
    const int qrow = qt * 128 + w * 16;
    float* ob = g_o + ((size_t)(b * TT) + qrow) * CC + h * DD;
    #pragma unroll
    for (int nt = 0; nt < 8; nt++) {
        const int d = nt * 8 + 2 * t4;
        *(float2*)(ob + (size_t)g * CC + d) =
            make_float2(to_tf32(o[nt][0] * i0), to_tf32(o[nt][1] * i0));
        *(float2*)(ob + (size_t)(g + 8) * CC + d) =
            make_float2(to_tf32(o[nt][2] * i1), to_tf32(o[nt][3] * i1));
    }
}

extern "C" void kernel_launch(void* const* d_in, const int* in_sizes, int n_in,
                              void* d_out, int out_size)
{
    const float* x      = (const float*)d_in[0];
    const float* w_qkv  = (const float*)d_in[1];
    const float* b_qkv  = (const float*)d_in[2];
    const float* w_proj = (const float*)d_in[3];
    const float* b_proj = (const float*)d_in[4];
    float* out = (float*)d_out;

    float *d_xr, *d_wq, *d_wp, *d_o;
    cudaGetSymbolAddress((void**)&d_xr, g_xr);
    cudaGetSymbolAddress((void**)&d_wq, g_wq);
    cudaGetSymbolAddress((void**)&d_wp, g_wp);
    cudaGetSymbolAddress((void**)&d_o,  g_o);

    cudaFuncSetAttribute(attn_tc, cudaFuncAttributeMaxDynamicSharedMemorySize,
                         ATTN_SMEM);

    // one-time tf32 pre-rounding (single fused launch)
    round_all<<<12288, 256>>>(x, d_xr, w_qkv, d_wq, w_proj, d_wp);

    dim3 g1(NQKV / 128, MROWS / 128);   // (24, 64)
    gemm_tf32<<<g1, 256>>>(d_xr, d_wq, b_qkv, nullptr, NQKV, 0);

    dim3 g2(TT / 128, HH, BB);          // (16, 16, 4)
    attn_tc<<<g2, 256, ATTN_SMEM>>>();

    dim3 g3(CC / 128, MROWS / 128);     // (8, 64)
    gemm_tf32<<<g3, 256>>>(d_o, d_wp, b_proj, out, CC, 1);
}